// round 15
// baseline (speedup 1.0000x reference)
#include <cuda_runtime.h>
#include <cuda_bf16.h>

#define S_LEN 1024
#define NP 513
#define PSTR 516
#define OUT_ELEMS 4194304
#define NROWS 65536
#define TW 72   // bf16 smem row stride (elements)

typedef unsigned long long ull;
typedef unsigned int u32;

__device__ float g_P[(size_t)NROWS * PSTR];   // P[row,p] = q[row]·Wk[p]
__device__ u32   g_Cp[(size_t)NROWS * PSTR];  // packed bf16 hi/lo of shifted E
__device__ __nv_bfloat16 gKh[OUT_ELEMS], gKl[OUT_ELEMS];
__device__ __nv_bfloat16 gVh[OUT_ELEMS], gVl[OUT_ELEMS];
__device__ __nv_bfloat16 gWrh[512 * 64], gWrl[512 * 64];  // Wv_rev split, [m][d]

// smem byte offsets for kernBCD (E aliases K; C/Wv chunks alias K/V)
#define QH_OFF 0
#define QL_OFF 9216
#define KH_OFF 18432
#define KL_OFF 27648
#define VH_OFF 36864
#define VL_OFF 46080
#define SS_OFF 55296
#define SCS_OFF 55552
#define SINV_OFF 55808
#define SWV0_OFF 56064
#define SMEM_BCD 56320

// smem byte offsets for kernA (tensor)
#define AQH_OFF 0
#define AQL_OFF 9216
#define AWH_OFF 18432
#define AWL_OFF 36864
#define SMEM_A 55296

// ---- tensor helpers ----
__device__ __forceinline__ void ldmx4(u32* r, u32 addr) {
    asm volatile("ldmatrix.sync.aligned.m8n8.x4.shared.b16 {%0,%1,%2,%3}, [%4];"
        : "=r"(r[0]), "=r"(r[1]), "=r"(r[2]), "=r"(r[3]) : "r"(addr));
}
__device__ __forceinline__ void ldmx2(u32* r, u32 addr) {
    asm volatile("ldmatrix.sync.aligned.m8n8.x2.shared.b16 {%0,%1}, [%2];"
        : "=r"(r[0]), "=r"(r[1]) : "r"(addr));
}
__device__ __forceinline__ void ldmx2t(u32* r, u32 addr) {
    asm volatile("ldmatrix.sync.aligned.m8n8.x2.trans.shared.b16 {%0,%1}, [%2];"
        : "=r"(r[0]), "=r"(r[1]) : "r"(addr));
}
__device__ __forceinline__ void mma16816(float* c, const u32* a, const u32* b) {
    asm volatile("mma.sync.aligned.m16n8k16.row.col.f32.bf16.bf16.f32 "
        "{%0,%1,%2,%3}, {%4,%5,%6,%7}, {%8,%9}, {%0,%1,%2,%3};"
        : "+f"(c[0]), "+f"(c[1]), "+f"(c[2]), "+f"(c[3])
        : "r"(a[0]), "r"(a[1]), "r"(a[2]), "r"(a[3]), "r"(b[0]), "r"(b[1]));
}
__device__ __forceinline__ void split2(float x, float y, u32& h, u32& l) {
    __nv_bfloat16 hx = __float2bfloat16(x), hy = __float2bfloat16(y);
    __nv_bfloat162 hh; hh.x = hx; hh.y = hy;
    __nv_bfloat162 ll;
    ll.x = __float2bfloat16(x - __bfloat162float(hx));
    ll.y = __float2bfloat16(y - __bfloat162float(hy));
    h = *(u32*)&hh; l = *(u32*)&ll;
}

// ---------------------------------------------------------------------------
// kernSplit: K,V fp32 -> global bf16 hi/lo (once)
// ---------------------------------------------------------------------------
__global__ void __launch_bounds__(256) kernSplit(const float* __restrict__ k,
                                                 const float* __restrict__ v) {
    const int idx = (blockIdx.x * 256 + threadIdx.x) * 4;
    float4 kv = *(const float4*)(k + idx);
    u32 h0, l0, h1, l1;
    split2(kv.x, kv.y, h0, l0); split2(kv.z, kv.w, h1, l1);
    *(uint2*)&gKh[idx] = make_uint2(h0, h1);
    *(uint2*)&gKl[idx] = make_uint2(l0, l1);
    float4 vv = *(const float4*)(v + idx);
    split2(vv.x, vv.y, h0, l0); split2(vv.z, vv.w, h1, l1);
    *(uint2*)&gVh[idx] = make_uint2(h0, h1);
    *(uint2*)&gVl[idx] = make_uint2(l0, l1);
}

// ---------------------------------------------------------------------------
// kernSplitW: Wv_rev[m][d] = Wv[512-m][d] -> bf16 hi/lo, m in [0,512)
// ---------------------------------------------------------------------------
__global__ void __launch_bounds__(256) kernSplitW(const float* __restrict__ Wv) {
    const int idx = (blockIdx.x * 256 + threadIdx.x) * 4;   // 512*64/4 = 8192 thr
    const int m = idx >> 6, d = idx & 63;
    float4 vv = *(const float4*)(Wv + (size_t)(512 - m) * 64 + d);
    u32 h0, l0, h1, l1;
    split2(vv.x, vv.y, h0, l0); split2(vv.z, vv.w, h1, l1);
    *(uint2*)&gWrh[idx] = make_uint2(h0, h1);
    *(uint2*)&gWrl[idx] = make_uint2(l0, l1);
}

// ---------------------------------------------------------------------------
// kernP512: g_P[row, 512] = q[row] · Wk[512]  (fp32 exact; diagonal bias)
// ---------------------------------------------------------------------------
__global__ void __launch_bounds__(256) kernP512(const float* __restrict__ q,
                                                const float* __restrict__ Wk) {
    __shared__ float w512[64];
    const int tid = threadIdx.x;
    if (tid < 64) w512[tid] = Wk[(size_t)512 * 64 + tid];
    __syncthreads();
    const int row = blockIdx.x * 256 + tid;
    const float* qr = q + (size_t)row * 64;
    float s = 0.f;
    #pragma unroll
    for (int c4 = 0; c4 < 64; c4 += 4) {
        float4 vv = *(const float4*)(qr + c4);
        s += vv.x * w512[c4] + vv.y * w512[c4+1] + vv.z * w512[c4+2] + vv.w * w512[c4+3];
    }
    g_P[(size_t)row * PSTR + 512] = s;
}

// ---------------------------------------------------------------------------
// Kernel A (tensor): P = Q @ Wk^T for p in [0,512), 64x128 tiles, bf16 3-split
// ---------------------------------------------------------------------------
__global__ void __launch_bounds__(256) kernA(const float* __restrict__ q,
                                             const float* __restrict__ Wk) {
    const int r0 = blockIdx.x * 64;
    const int p0 = blockIdx.y * 128;
    const int i0 = r0 & (S_LEN - 1);
    if (p0 + 127 < 449 - i0) return;
    extern __shared__ char smemA[];
    __nv_bfloat16* Qh = (__nv_bfloat16*)(smemA + AQH_OFF);
    __nv_bfloat16* Ql = (__nv_bfloat16*)(smemA + AQL_OFF);
    __nv_bfloat16* Wh = (__nv_bfloat16*)(smemA + AWH_OFF);
    __nv_bfloat16* Wl = (__nv_bfloat16*)(smemA + AWL_OFF);
    const u32 sbase = (u32)__cvta_generic_to_shared(smemA);
    const int tid = threadIdx.x;
    const int wid = tid >> 5, lane = tid & 31;

    #pragma unroll
    for (int l = 0; l < 4; ++l) {
        int e = tid + l * 256;
        int r = e >> 4, c4 = (e & 15) << 2;
        float4 vv = *(const float4*)(q + (size_t)(r0 + r) * 64 + c4);
        u32 h0, l0, h1, l1;
        split2(vv.x, vv.y, h0, l0); split2(vv.z, vv.w, h1, l1);
        *(u32*)&Qh[r*TW + c4] = h0; *(u32*)&Qh[r*TW + c4 + 2] = h1;
        *(u32*)&Ql[r*TW + c4] = l0; *(u32*)&Ql[r*TW + c4 + 2] = l1;
    }
    #pragma unroll
    for (int l = 0; l < 8; ++l) {
        int e = tid + l * 256;
        int r = e >> 4, c4 = (e & 15) << 2;
        float4 vv = *(const float4*)(Wk + (size_t)(p0 + r) * 64 + c4);
        u32 h0, l0, h1, l1;
        split2(vv.x, vv.y, h0, l0); split2(vv.z, vv.w, h1, l1);
        *(u32*)&Wh[r*TW + c4] = h0; *(u32*)&Wh[r*TW + c4 + 2] = h1;
        *(u32*)&Wl[r*TW + c4] = l0; *(u32*)&Wl[r*TW + c4 + 2] = l1;
    }
    __syncthreads();

    const int mrow = 16 * (wid & 3);
    const int n0   = 64 * (wid >> 2);
    const int lA_r = (lane & 7) + ((lane >> 3) & 1) * 8;
    const int lA_c = ((lane >> 4) & 1) * 8;
    const int lB_r = (lane & 7);
    const int lB_c = ((lane >> 3) & 1) * 8;

    float accP[8][4] = {};
    #pragma unroll
    for (int ks = 0; ks < 4; ++ks) {
        u32 ah[4], al[4], bh2[2], bl2[2];
        ldmx4(ah, sbase + AQH_OFF + (u32)((mrow + lA_r)*TW + ks*16 + lA_c)*2);
        ldmx4(al, sbase + AQL_OFF + (u32)((mrow + lA_r)*TW + ks*16 + lA_c)*2);
        #pragma unroll
        for (int nt = 0; nt < 8; ++nt) {
            ldmx2(bh2, sbase + AWH_OFF + (u32)((n0 + 8*nt + lB_r)*TW + ks*16 + lB_c)*2);
            ldmx2(bl2, sbase + AWL_OFF + (u32)((n0 + 8*nt + lB_r)*TW + ks*16 + lB_c)*2);
            mma16816(accP[nt], ah, bh2);
            mma16816(accP[nt], ah, bl2);
            mma16816(accP[nt], al, bh2);
        }
    }

    const int r1 = mrow + (lane >> 2), r2 = r1 + 8;
    const size_t row1 = (size_t)(r0 + r1) * PSTR;
    const size_t row2 = (size_t)(r0 + r2) * PSTR;
    #pragma unroll
    for (int nt = 0; nt < 8; ++nt) {
        const int p = p0 + n0 + 8*nt + 2*(lane & 3);
        *(float2*)(g_P + row1 + p) = make_float2(accP[nt][0], accP[nt][1]);
        *(float2*)(g_P + row2 + p) = make_float2(accP[nt][2], accP[nt][3]);
    }
}

// ---------------------------------------------------------------------------
// Fused B+C+D: all three GEMMs on tensor cores; D accumulates into accO.
// ---------------------------------------------------------------------------
__global__ void __launch_bounds__(256, 4) kernBCD(const float* __restrict__ q,
                                                  const float* __restrict__ Wv,
                                                  float* __restrict__ wbuf,
                                                  float* __restrict__ outp) {
    extern __shared__ char smem[];
    __nv_bfloat16* Qh = (__nv_bfloat16*)(smem + QH_OFF);
    __nv_bfloat16* Ql = (__nv_bfloat16*)(smem + QL_OFF);
    __nv_bfloat16* Kh = (__nv_bfloat16*)(smem + KH_OFF);   // K^T; E; C-chunk
    __nv_bfloat16* Kl = (__nv_bfloat16*)(smem + KL_OFF);
    __nv_bfloat16* Vh = (__nv_bfloat16*)(smem + VH_OFF);   // V; Wv-chunk
    __nv_bfloat16* Vl = (__nv_bfloat16*)(smem + VL_OFF);
    float* sS   = (float*)(smem + SS_OFF);
    float* sCs  = (float*)(smem + SCS_OFF);
    float* sInv = (float*)(smem + SINV_OFF);
    float* sWv0 = (float*)(smem + SWV0_OFF);
    const u32 sbase = (u32)__cvta_generic_to_shared(smem);

    const int bh = blockIdx.y;
    const int ib = 15 - (int)blockIdx.x;
    const int i0 = ib * 64;
    const int rowbase = bh * S_LEN + i0;
    const int tid = threadIdx.x;
    const int wid = tid >> 5, lane = tid & 31;
    const int mrow = 16 * (wid & 3);
    const int n0   = 32 * (wid >> 2);

    // ---- Q prep: split into Qh/Ql ----
    #pragma unroll
    for (int l = 0; l < 4; ++l) {
        int e = tid + l * 256;
        int r = e >> 4, c4 = (e & 15) << 2;
        float4 vv = *(const float4*)(q + (size_t)(rowbase + r) * 64 + c4);
        u32 h0, l0, h1, l1;
        split2(vv.x, vv.y, h0, l0); split2(vv.z, vv.w, h1, l1);
        *(u32*)&Qh[r*TW + c4] = h0; *(u32*)&Qh[r*TW + c4 + 2] = h1;
        *(u32*)&Ql[r*TW + c4] = l0; *(u32*)&Ql[r*TW + c4 + 2] = l1;
    }
    if (tid < 64) { sS[tid] = 0.f; sCs[tid] = 0.f; }

    const int r1 = mrow + (lane >> 2), r2 = r1 + 8;
    const int i1 = i0 + r1, i2 = i0 + r2;
    const size_t prow1 = (size_t)(rowbase + r1) * PSTR;
    const size_t prow2 = (size_t)(rowbase + r2) * PSTR;
    const size_t wrow1 = (size_t)(rowbase + r1) * S_LEN;
    const size_t wrow2 = (size_t)(rowbase + r2) * S_LEN;

    const int lA_r = (lane & 7) + ((lane >> 3) & 1) * 8;
    const int lA_c = ((lane >> 4) & 1) * 8;
    const int lB_r = (lane & 7);
    const int lB_c = ((lane >> 3) & 1) * 8;
    const int lBt_r = (lane & 7) + ((lane >> 3) & 1) * 8;

    float accO[4][4] = {};   // E@V + C@Wv_rev accumulators

    // ================= pass1 =================
    for (int jb = 0; jb <= ib; ++jb) {
        const int j0 = jb * 64;
        __syncthreads();   // (1) prev E@V mma done

        #pragma unroll
        for (int l = 0; l < 2; ++l) {
            int e = tid + l * 256;
            int r = e >> 3, c8 = (e & 7) << 3;
            const size_t ga = (size_t)(bh*S_LEN + j0 + r)*64 + c8;
            *(uint4*)&Kh[r*TW + c8] = *(const uint4*)&gKh[ga];
            *(uint4*)&Kl[r*TW + c8] = *(const uint4*)&gKl[ga];
            *(uint4*)&Vh[r*TW + c8] = *(const uint4*)&gVh[ga];
            *(uint4*)&Vl[r*TW + c8] = *(const uint4*)&gVl[ga];
        }
        __syncthreads();   // (2) tiles ready

        // ---- QK^T via mma ----
        float accC[4][4] = {};
        #pragma unroll
        for (int ks = 0; ks < 4; ++ks) {
            u32 ah[4], al[4], bh2[2], bl2[2];
            ldmx4(ah, sbase + QH_OFF + (u32)((mrow + lA_r)*TW + ks*16 + lA_c)*2);
            ldmx4(al, sbase + QL_OFF + (u32)((mrow + lA_r)*TW + ks*16 + lA_c)*2);
            #pragma unroll
            for (int nt = 0; nt < 4; ++nt) {
                ldmx2(bh2, sbase + KH_OFF + (u32)((n0 + 8*nt + lB_r)*TW + ks*16 + lB_c)*2);
                ldmx2(bl2, sbase + KL_OFF + (u32)((n0 + 8*nt + lB_r)*TW + ks*16 + lB_c)*2);
                mma16816(accC[nt], ah, bh2);
                mma16816(accC[nt], ah, bl2);
                mma16816(accC[nt], al, bh2);
            }
        }
        __syncthreads();   // (3) K reads done -> E may overwrite Kh/Kl

        // ---- bias + mask + exp + rowsum + packed scatter + E->smem ----
        float s1 = 0.f, s2 = 0.f;
        #pragma unroll
        for (int nt = 0; nt < 4; ++nt) {
            const int jl = n0 + 8*nt + 2*(lane & 3);
            const int j  = j0 + jl;
            {
                int p0c = j - i1 + 512;   if (p0c < 0) p0c = 0;
                int p1c = j + 1 - i1 + 512; if (p1c < 0) p1c = 0;
                float l0 = accC[nt][0] + g_P[prow1 + p0c];
                float l1 = accC[nt][1] + g_P[prow1 + p1c];
                if (j     > i1) l0 = -1e30f;
                if (j + 1 > i1) l1 = -1e30f;
                float e0 = __expf(l0), e1 = __expf(l1);
                s1 += e0 + e1;
                u32 hh, ll; split2(e0, e1, hh, ll);
                *(u32*)&Kh[r1*TW + jl] = hh;
                *(u32*)&Kl[r1*TW + jl] = ll;
                const u32 pk0 = (hh & 0xFFFFu) | (ll << 16);
                const u32 pk1 = (hh >> 16) | (ll & 0xFFFF0000u);
                int mm = i1 - j;
                if (mm >= 0) {
                    if (mm < 512) g_Cp[prow1 + mm] = pk0;
                    else { atomicAdd(&sCs[r1], e0); wbuf[wrow1 + j] = e0; }
                }
                if (mm - 1 >= 0) {
                    if (mm - 1 < 512) g_Cp[prow1 + mm - 1] = pk1;
                    else { atomicAdd(&sCs[r1], e1); wbuf[wrow1 + j + 1] = e1; }
                }
            }
            {
                int p0c = j - i2 + 512;   if (p0c < 0) p0c = 0;
                int p1c = j + 1 - i2 + 512; if (p1c < 0) p1c = 0;
                float l0 = accC[nt][2] + g_P[prow2 + p0c];
                float l1 = accC[nt][3] + g_P[prow2 + p1c];
                if (j     > i2) l0 = -1e30f;
                if (j + 1 > i2) l1 = -1e30f;
                float e0 = __expf(l0), e1 = __expf(l1);
                s2 += e0 + e1;
                u32 hh, ll; split2(e0, e1, hh, ll);
                *(u32*)&Kh[r2*TW + jl] = hh;
                *(u32*)&Kl[r2*TW + jl] = ll;
                const u32 pk0 = (hh & 0xFFFFu) | (ll << 16);
                const u32 pk1 = (hh >> 16) | (ll & 0xFFFF0000u);
                int mm = i2 - j;
                if (mm >= 0) {
                    if (mm < 512) g_Cp[prow2 + mm] = pk0;
                    else { atomicAdd(&sCs[r2], e0); wbuf[wrow2 + j] = e0; }
                }
                if (mm - 1 >= 0) {
                    if (mm - 1 < 512) g_Cp[prow2 + mm - 1] = pk1;
                    else { atomicAdd(&sCs[r2], e1); wbuf[wrow2 + j + 1] = e1; }
                }
            }
        }
        s1 += __shfl_xor_sync(0xffffffffu, s1, 1);
        s1 += __shfl_xor_sync(0xffffffffu, s1, 2);
        s2 += __shfl_xor_sync(0xffffffffu, s2, 1);
        s2 += __shfl_xor_sync(0xffffffffu, s2, 2);
        if ((lane & 3) == 0) { atomicAdd(&sS[r1], s1); atomicAdd(&sS[r2], s2); }

        __syncthreads();   // (4) E tiles ready

        // ---- accO += E @ V via mma (E aliased in Kh/Kl) ----
        #pragma unroll
        for (int ks = 0; ks < 4; ++ks) {
            u32 ah[4], al[4], bh2[2], bl2[2];
            ldmx4(ah, sbase + KH_OFF + (u32)((mrow + lA_r)*TW + ks*16 + lA_c)*2);
            ldmx4(al, sbase + KL_OFF + (u32)((mrow + lA_r)*TW + ks*16 + lA_c)*2);
            #pragma unroll
            for (int nt = 0; nt < 4; ++nt) {
                ldmx2t(bh2, sbase + VH_OFF + (u32)((ks*16 + lBt_r)*TW + n0 + 8*nt)*2);
                ldmx2t(bl2, sbase + VL_OFF + (u32)((ks*16 + lBt_r)*TW + n0 + 8*nt)*2);
                mma16816(accO[nt], ah, bh2);
                mma16816(accO[nt], ah, bl2);
                mma16816(accO[nt], al, bh2);
            }
        }
    }

    __syncthreads();
    if (tid < 64) {
        sInv[tid] = 1.0f / sS[tid];
        sWv0[tid] = Wv[tid];   // Wv_rev[512] = Wv[0][:]
    }

    // ---- D-phase (mma into accO): m in [0, min(512, i0+64)) ----
    const int mEndD = min(512, i0 + 64);
    for (int m0 = 0; m0 < mEndD; m0 += 64) {
        __syncthreads();   // buffers free
        // C chunk: unpack g_Cp -> Kh/Kl, mask m > irow
        #pragma unroll
        for (int l = 0; l < 4; ++l) {
            int e = tid + l * 256;
            int r = e >> 4, m4 = (e & 15) << 2;
            const int irow = i0 + r;
            const int mb = m0 + m4;
            uint4 pp = *(const uint4*)(g_Cp + (size_t)(rowbase + r)*PSTR + mb);
            u32 pa[4] = {pp.x, pp.y, pp.z, pp.w};
            #pragma unroll
            for (int t = 0; t < 4; ++t)
                if (mb + t > irow) pa[t] = 0;
            *(u32*)&Kh[r*TW + m4]     = (pa[0] & 0xFFFFu) | ((pa[1] & 0xFFFFu) << 16);
            *(u32*)&Kh[r*TW + m4 + 2] = (pa[2] & 0xFFFFu) | ((pa[3] & 0xFFFFu) << 16);
            *(u32*)&Kl[r*TW + m4]     = (pa[0] >> 16) | (pa[1] & 0xFFFF0000u);
            *(u32*)&Kl[r*TW + m4 + 2] = (pa[2] >> 16) | (pa[3] & 0xFFFF0000u);
        }
        // Wv_rev chunk: pre-split, pure copy
        #pragma unroll
        for (int l = 0; l < 2; ++l) {
            int e = tid + l * 256;
            int mr = e >> 3, c8 = (e & 7) << 3;
            const size_t ga = (size_t)(m0 + mr)*64 + c8;
            *(uint4*)&Vh[mr*TW + c8] = *(const uint4*)&gWrh[ga];
            *(uint4*)&Vl[mr*TW + c8] = *(const uint4*)&gWrl[ga];
        }
        __syncthreads();
        #pragma unroll
        for (int ks = 0; ks < 4; ++ks) {
            u32 ah[4], al[4], bh2[2], bl2[2];
            ldmx4(ah, sbase + KH_OFF + (u32)((mrow + lA_r)*TW + ks*16 + lA_c)*2);
            ldmx4(al, sbase + KL_OFF + (u32)((mrow + lA_r)*TW + ks*16 + lA_c)*2);
            #pragma unroll
            for (int nt = 0; nt < 4; ++nt) {
                ldmx2t(bh2, sbase + VH_OFF + (u32)((ks*16 + lBt_r)*TW + n0 + 8*nt)*2);
                ldmx2t(bl2, sbase + VL_OFF + (u32)((ks*16 + lBt_r)*TW + n0 + 8*nt)*2);
                mma16816(accO[nt], ah, bh2);
                mma16816(accO[nt], ah, bl2);
                mma16816(accO[nt], al, bh2);
            }
        }
    }
    __syncthreads();   // sInv/sCs/sWv0 stable

    // ---- final output directly from fragments ----
    {
        const float inv1 = sInv[r1], inv2 = sInv[r2];
        const float cs1 = sCs[r1],  cs2 = sCs[r2];
        #pragma unroll
        for (int nt = 0; nt < 4; ++nt) {
            const int c = n0 + 8*nt + 2*(lane & 3);
            const float w00 = (accO[nt][0] + cs1*sWv0[c])   * inv1;
            const float w01 = (accO[nt][1] + cs1*sWv0[c+1]) * inv1;
            const float w10 = (accO[nt][2] + cs2*sWv0[c])   * inv2;
            const float w11 = (accO[nt][3] + cs2*sWv0[c+1]) * inv2;
            *(float2*)(outp + (size_t)(rowbase + r1)*64 + c) = make_float2(w00, w01);
            *(float2*)(outp + (size_t)(rowbase + r2)*64 + c) = make_float2(w10, w11);
        }
    }

    // ---- pass2: weights from g_Cp (unpack hi+lo) ----
    for (int jb = 0; jb < 16; ++jb) {
        const int j0 = jb * 64;
        if (jb > ib) {
            const float4 z = make_float4(0.f, 0.f, 0.f, 0.f);
            for (int e = tid; e < 1024; e += 256) {
                int r = e >> 4, c4 = (e & 15) << 2;
                *(float4*)(wbuf + (size_t)(rowbase + r) * S_LEN + j0 + c4) = z;
            }
            continue;
        }
        for (int e = tid; e < 1024; e += 256) {
            int r = e >> 4, c4 = (e & 15) << 2;
            const int i = i0 + r;
            const size_t row = (size_t)(rowbase + r);
            const size_t addr = row * S_LEN + j0 + c4;
            const size_t prow = row * PSTR;
            const float f = sInv[r];
            float w[4];
            #pragma unroll
            for (int t = 0; t < 4; ++t) {
                const int j = j0 + c4 + t;
                const int mm = i - j;
                float eV = 0.f;
                if (mm >= 0) {
                    if (mm < 512) {
                        const u32 p = g_Cp[prow + mm];
                        eV = __uint_as_float(p << 16) + __uint_as_float(p & 0xFFFF0000u);
                    } else {
                        eV = wbuf[addr + t];   // raw E written in pass1
                    }
                }
                w[t] = eV * f;
            }
            *(float4*)(wbuf + addr) = make_float4(w[0], w[1], w[2], w[3]);
        }
    }
}

// ---------------------------------------------------------------------------
extern "C" void kernel_launch(void* const* d_in, const int* in_sizes, int n_in,
                              void* d_out, int out_size) {
    const float* q  = (const float*)d_in[0];
    const float* k  = (const float*)d_in[1];
    const float* v  = (const float*)d_in[2];
    const float* Wk = (const float*)d_in[3];
    const float* Wv = (const float*)d_in[4];

    float* outp = (float*)d_out;            // (B,H,S,D)
    float* wbuf = outp + OUT_ELEMS;         // (B,H,S,S) weights

    static bool attrs_set = false;
    if (!attrs_set) {
        cudaFuncSetAttribute(kernA,   cudaFuncAttributeMaxDynamicSharedMemorySize, SMEM_A);
        cudaFuncSetAttribute(kernBCD, cudaFuncAttributeMaxDynamicSharedMemorySize, SMEM_BCD);
        attrs_set = true;
    }
    kernSplit<<<4096, 256>>>(k, v);
    kernSplitW<<<32, 256>>>(Wv);
    kernP512<<<256, 256>>>(q, Wk);
    kernA<<<dim3(1024, 4), 256, SMEM_A>>>(q, Wk);
    kernBCD<<<dim3(16, 64), 256, SMEM_BCD>>>(q, Wv, wbuf, outp);
}

// round 16
// speedup vs baseline: 1.0292x; 1.0292x over previous
#include <cuda_runtime.h>
#include <cuda_bf16.h>

#define S_LEN 1024
#define NP 513
#define PSTR 516
#define OUT_ELEMS 4194304
#define NROWS 65536
#define TW 72   // bf16 smem row stride (elements)

typedef unsigned long long ull;
typedef unsigned int u32;

__device__ float g_P[(size_t)NROWS * PSTR];   // P[row,p] = q[row]·Wk[p]
__device__ u32   g_Cp[(size_t)NROWS * PSTR];  // packed bf16 hi/lo of shifted E
__device__ __nv_bfloat16 gKh[OUT_ELEMS], gKl[OUT_ELEMS];
__device__ __nv_bfloat16 gVh[OUT_ELEMS], gVl[OUT_ELEMS];
__device__ __nv_bfloat16 gWrh[512 * 64], gWrl[512 * 64];  // Wv_rev split, [m][d]

// smem byte offsets for kernBCD (E aliases K; C/Wv chunks alias K/V)
#define QH_OFF 0
#define QL_OFF 9216
#define KH_OFF 18432
#define KL_OFF 27648
#define VH_OFF 36864
#define VL_OFF 46080
#define SS_OFF 55296
#define SCS_OFF 55552
#define SINV_OFF 55808
#define SWV0_OFF 56064
#define SMEM_BCD 56320

// smem byte offsets for kernA (tensor)
#define AQH_OFF 0
#define AQL_OFF 9216
#define AWH_OFF 18432
#define AWL_OFF 36864
#define SMEM_A 55296

// ---- tensor helpers ----
__device__ __forceinline__ void ldmx4(u32* r, u32 addr) {
    asm volatile("ldmatrix.sync.aligned.m8n8.x4.shared.b16 {%0,%1,%2,%3}, [%4];"
        : "=r"(r[0]), "=r"(r[1]), "=r"(r[2]), "=r"(r[3]) : "r"(addr));
}
__device__ __forceinline__ void ldmx2(u32* r, u32 addr) {
    asm volatile("ldmatrix.sync.aligned.m8n8.x2.shared.b16 {%0,%1}, [%2];"
        : "=r"(r[0]), "=r"(r[1]) : "r"(addr));
}
__device__ __forceinline__ void ldmx2t(u32* r, u32 addr) {
    asm volatile("ldmatrix.sync.aligned.m8n8.x2.trans.shared.b16 {%0,%1}, [%2];"
        : "=r"(r[0]), "=r"(r[1]) : "r"(addr));
}
__device__ __forceinline__ void mma16816(float* c, const u32* a, const u32* b) {
    asm volatile("mma.sync.aligned.m16n8k16.row.col.f32.bf16.bf16.f32 "
        "{%0,%1,%2,%3}, {%4,%5,%6,%7}, {%8,%9}, {%0,%1,%2,%3};"
        : "+f"(c[0]), "+f"(c[1]), "+f"(c[2]), "+f"(c[3])
        : "r"(a[0]), "r"(a[1]), "r"(a[2]), "r"(a[3]), "r"(b[0]), "r"(b[1]));
}
__device__ __forceinline__ void split2(float x, float y, u32& h, u32& l) {
    __nv_bfloat16 hx = __float2bfloat16(x), hy = __float2bfloat16(y);
    __nv_bfloat162 hh; hh.x = hx; hh.y = hy;
    __nv_bfloat162 ll;
    ll.x = __float2bfloat16(x - __bfloat162float(hx));
    ll.y = __float2bfloat16(y - __bfloat162float(hy));
    h = *(u32*)&hh; l = *(u32*)&ll;
}

// ---------------------------------------------------------------------------
// kernSplit: K,V fp32 -> global bf16 hi/lo (once)
// ---------------------------------------------------------------------------
__global__ void __launch_bounds__(256) kernSplit(const float* __restrict__ k,
                                                 const float* __restrict__ v) {
    const int idx = (blockIdx.x * 256 + threadIdx.x) * 4;
    float4 kv = *(const float4*)(k + idx);
    u32 h0, l0, h1, l1;
    split2(kv.x, kv.y, h0, l0); split2(kv.z, kv.w, h1, l1);
    *(uint2*)&gKh[idx] = make_uint2(h0, h1);
    *(uint2*)&gKl[idx] = make_uint2(l0, l1);
    float4 vv = *(const float4*)(v + idx);
    split2(vv.x, vv.y, h0, l0); split2(vv.z, vv.w, h1, l1);
    *(uint2*)&gVh[idx] = make_uint2(h0, h1);
    *(uint2*)&gVl[idx] = make_uint2(l0, l1);
}

// ---------------------------------------------------------------------------
// kernSplitW: Wv_rev[m][d] = Wv[512-m][d] -> bf16 hi/lo, m in [0,512)
// ---------------------------------------------------------------------------
__global__ void __launch_bounds__(256) kernSplitW(const float* __restrict__ Wv) {
    const int idx = (blockIdx.x * 256 + threadIdx.x) * 4;   // 8192 threads total
    const int m = idx >> 6, d = idx & 63;
    float4 vv = *(const float4*)(Wv + (size_t)(512 - m) * 64 + d);
    u32 h0, l0, h1, l1;
    split2(vv.x, vv.y, h0, l0); split2(vv.z, vv.w, h1, l1);
    *(uint2*)&gWrh[idx] = make_uint2(h0, h1);
    *(uint2*)&gWrl[idx] = make_uint2(l0, l1);
}

// ---------------------------------------------------------------------------
// kernP512: g_P[row, 512] = q[row] · Wk[512]  (fp32 exact; diagonal bias)
// ---------------------------------------------------------------------------
__global__ void __launch_bounds__(256) kernP512(const float* __restrict__ q,
                                                const float* __restrict__ Wk) {
    __shared__ float w512[64];
    const int tid = threadIdx.x;
    if (tid < 64) w512[tid] = Wk[(size_t)512 * 64 + tid];
    __syncthreads();
    const int row = blockIdx.x * 256 + tid;
    const float* qr = q + (size_t)row * 64;
    float s = 0.f;
    #pragma unroll
    for (int c4 = 0; c4 < 64; c4 += 4) {
        float4 vv = *(const float4*)(qr + c4);
        s += vv.x * w512[c4] + vv.y * w512[c4+1] + vv.z * w512[c4+2] + vv.w * w512[c4+3];
    }
    g_P[(size_t)row * PSTR + 512] = s;
}

// ---------------------------------------------------------------------------
// Kernel A (tensor): P = Q @ Wk^T for p in [0,512), 64x128 tiles, bf16 3-split
// ---------------------------------------------------------------------------
__global__ void __launch_bounds__(256) kernA(const float* __restrict__ q,
                                             const float* __restrict__ Wk) {
    const int r0 = blockIdx.x * 64;
    const int p0 = blockIdx.y * 128;
    const int i0 = r0 & (S_LEN - 1);
    if (p0 + 127 < 449 - i0) return;
    extern __shared__ char smemA[];
    __nv_bfloat16* Qh = (__nv_bfloat16*)(smemA + AQH_OFF);
    __nv_bfloat16* Ql = (__nv_bfloat16*)(smemA + AQL_OFF);
    __nv_bfloat16* Wh = (__nv_bfloat16*)(smemA + AWH_OFF);
    __nv_bfloat16* Wl = (__nv_bfloat16*)(smemA + AWL_OFF);
    const u32 sbase = (u32)__cvta_generic_to_shared(smemA);
    const int tid = threadIdx.x;
    const int wid = tid >> 5, lane = tid & 31;

    #pragma unroll
    for (int l = 0; l < 4; ++l) {
        int e = tid + l * 256;
        int r = e >> 4, c4 = (e & 15) << 2;
        float4 vv = *(const float4*)(q + (size_t)(r0 + r) * 64 + c4);
        u32 h0, l0, h1, l1;
        split2(vv.x, vv.y, h0, l0); split2(vv.z, vv.w, h1, l1);
        *(u32*)&Qh[r*TW + c4] = h0; *(u32*)&Qh[r*TW + c4 + 2] = h1;
        *(u32*)&Ql[r*TW + c4] = l0; *(u32*)&Ql[r*TW + c4 + 2] = l1;
    }
    #pragma unroll
    for (int l = 0; l < 8; ++l) {
        int e = tid + l * 256;
        int r = e >> 4, c4 = (e & 15) << 2;
        float4 vv = *(const float4*)(Wk + (size_t)(p0 + r) * 64 + c4);
        u32 h0, l0, h1, l1;
        split2(vv.x, vv.y, h0, l0); split2(vv.z, vv.w, h1, l1);
        *(u32*)&Wh[r*TW + c4] = h0; *(u32*)&Wh[r*TW + c4 + 2] = h1;
        *(u32*)&Wl[r*TW + c4] = l0; *(u32*)&Wl[r*TW + c4 + 2] = l1;
    }
    __syncthreads();

    const int mrow = 16 * (wid & 3);
    const int n0   = 64 * (wid >> 2);
    const int lA_r = (lane & 7) + ((lane >> 3) & 1) * 8;
    const int lA_c = ((lane >> 4) & 1) * 8;
    const int lB_r = (lane & 7);
    const int lB_c = ((lane >> 3) & 1) * 8;

    float accP[8][4] = {};
    #pragma unroll
    for (int ks = 0; ks < 4; ++ks) {
        u32 ah[4], al[4], bh2[2], bl2[2];
        ldmx4(ah, sbase + AQH_OFF + (u32)((mrow + lA_r)*TW + ks*16 + lA_c)*2);
        ldmx4(al, sbase + AQL_OFF + (u32)((mrow + lA_r)*TW + ks*16 + lA_c)*2);
        #pragma unroll
        for (int nt = 0; nt < 8; ++nt) {
            ldmx2(bh2, sbase + AWH_OFF + (u32)((n0 + 8*nt + lB_r)*TW + ks*16 + lB_c)*2);
            ldmx2(bl2, sbase + AWL_OFF + (u32)((n0 + 8*nt + lB_r)*TW + ks*16 + lB_c)*2);
            mma16816(accP[nt], ah, bh2);
            mma16816(accP[nt], ah, bl2);
            mma16816(accP[nt], al, bh2);
        }
    }

    const int r1 = mrow + (lane >> 2), r2 = r1 + 8;
    const size_t row1 = (size_t)(r0 + r1) * PSTR;
    const size_t row2 = (size_t)(r0 + r2) * PSTR;
    #pragma unroll
    for (int nt = 0; nt < 8; ++nt) {
        const int p = p0 + n0 + 8*nt + 2*(lane & 3);
        *(float2*)(g_P + row1 + p) = make_float2(accP[nt][0], accP[nt][1]);
        *(float2*)(g_P + row2 + p) = make_float2(accP[nt][2], accP[nt][3]);
    }
}

// ---------------------------------------------------------------------------
// Fused B+C+D: all three GEMMs on tensor cores; D accumulates into accO.
// ---------------------------------------------------------------------------
__global__ void __launch_bounds__(256) kernBCD(const float* __restrict__ q,
                                               const float* __restrict__ Wv,
                                               float* __restrict__ wbuf,
                                               float* __restrict__ outp) {
    extern __shared__ char smem[];
    __nv_bfloat16* Qh = (__nv_bfloat16*)(smem + QH_OFF);
    __nv_bfloat16* Ql = (__nv_bfloat16*)(smem + QL_OFF);
    __nv_bfloat16* Kh = (__nv_bfloat16*)(smem + KH_OFF);   // K^T; E; C-chunk
    __nv_bfloat16* Kl = (__nv_bfloat16*)(smem + KL_OFF);
    __nv_bfloat16* Vh = (__nv_bfloat16*)(smem + VH_OFF);   // V; Wv-chunk
    __nv_bfloat16* Vl = (__nv_bfloat16*)(smem + VL_OFF);
    float* sS   = (float*)(smem + SS_OFF);
    float* sCs  = (float*)(smem + SCS_OFF);
    float* sInv = (float*)(smem + SINV_OFF);
    float* sWv0 = (float*)(smem + SWV0_OFF);
    const u32 sbase = (u32)__cvta_generic_to_shared(smem);

    const int bh = blockIdx.y;
    const int ib = 15 - (int)blockIdx.x;
    const int i0 = ib * 64;
    const int rowbase = bh * S_LEN + i0;
    const int tid = threadIdx.x;
    const int wid = tid >> 5, lane = tid & 31;
    const int mrow = 16 * (wid & 3);
    const int n0   = 32 * (wid >> 2);

    // ---- Q prep: split into Qh/Ql ----
    #pragma unroll
    for (int l = 0; l < 4; ++l) {
        int e = tid + l * 256;
        int r = e >> 4, c4 = (e & 15) << 2;
        float4 vv = *(const float4*)(q + (size_t)(rowbase + r) * 64 + c4);
        u32 h0, l0, h1, l1;
        split2(vv.x, vv.y, h0, l0); split2(vv.z, vv.w, h1, l1);
        *(u32*)&Qh[r*TW + c4] = h0; *(u32*)&Qh[r*TW + c4 + 2] = h1;
        *(u32*)&Ql[r*TW + c4] = l0; *(u32*)&Ql[r*TW + c4 + 2] = l1;
    }
    if (tid < 64) { sS[tid] = 0.f; sCs[tid] = 0.f; }

    const int r1 = mrow + (lane >> 2), r2 = r1 + 8;
    const int i1 = i0 + r1, i2 = i0 + r2;
    const size_t prow1 = (size_t)(rowbase + r1) * PSTR;
    const size_t prow2 = (size_t)(rowbase + r2) * PSTR;
    const size_t wrow1 = (size_t)(rowbase + r1) * S_LEN;
    const size_t wrow2 = (size_t)(rowbase + r2) * S_LEN;

    const int lA_r = (lane & 7) + ((lane >> 3) & 1) * 8;
    const int lA_c = ((lane >> 4) & 1) * 8;
    const int lB_r = (lane & 7);
    const int lB_c = ((lane >> 3) & 1) * 8;
    const int lBt_r = (lane & 7) + ((lane >> 3) & 1) * 8;

    float accO[4][4] = {};   // E@V + C@Wv_rev accumulators

    // ================= pass1 =================
    for (int jb = 0; jb <= ib; ++jb) {
        const int j0 = jb * 64;
        __syncthreads();   // (1) prev E@V mma done

        #pragma unroll
        for (int l = 0; l < 2; ++l) {
            int e = tid + l * 256;
            int r = e >> 3, c8 = (e & 7) << 3;
            const size_t ga = (size_t)(bh*S_LEN + j0 + r)*64 + c8;
            *(uint4*)&Kh[r*TW + c8] = *(const uint4*)&gKh[ga];
            *(uint4*)&Kl[r*TW + c8] = *(const uint4*)&gKl[ga];
            *(uint4*)&Vh[r*TW + c8] = *(const uint4*)&gVh[ga];
            *(uint4*)&Vl[r*TW + c8] = *(const uint4*)&gVl[ga];
        }
        __syncthreads();   // (2) tiles ready

        // ---- QK^T via mma ----
        float accC[4][4] = {};
        #pragma unroll
        for (int ks = 0; ks < 4; ++ks) {
            u32 ah[4], al[4], bh2[2], bl2[2];
            ldmx4(ah, sbase + QH_OFF + (u32)((mrow + lA_r)*TW + ks*16 + lA_c)*2);
            ldmx4(al, sbase + QL_OFF + (u32)((mrow + lA_r)*TW + ks*16 + lA_c)*2);
            #pragma unroll
            for (int nt = 0; nt < 4; ++nt) {
                ldmx2(bh2, sbase + KH_OFF + (u32)((n0 + 8*nt + lB_r)*TW + ks*16 + lB_c)*2);
                ldmx2(bl2, sbase + KL_OFF + (u32)((n0 + 8*nt + lB_r)*TW + ks*16 + lB_c)*2);
                mma16816(accC[nt], ah, bh2);
                mma16816(accC[nt], ah, bl2);
                mma16816(accC[nt], al, bh2);
            }
        }
        __syncthreads();   // (3) K reads done -> E may overwrite Kh/Kl

        // ---- bias + mask + exp + rowsum + packed scatter + E->smem ----
        float s1 = 0.f, s2 = 0.f;
        #pragma unroll
        for (int nt = 0; nt < 4; ++nt) {
            const int jl = n0 + 8*nt + 2*(lane & 3);
            const int j  = j0 + jl;
            {
                int p0c = j - i1 + 512;   if (p0c < 0) p0c = 0;
                int p1c = j + 1 - i1 + 512; if (p1c < 0) p1c = 0;
                float l0 = accC[nt][0] + g_P[prow1 + p0c];
                float l1 = accC[nt][1] + g_P[prow1 + p1c];
                if (j     > i1) l0 = -1e30f;
                if (j + 1 > i1) l1 = -1e30f;
                float e0 = __expf(l0), e1 = __expf(l1);
                s1 += e0 + e1;
                u32 hh, ll; split2(e0, e1, hh, ll);
                *(u32*)&Kh[r1*TW + jl] = hh;
                *(u32*)&Kl[r1*TW + jl] = ll;
                const u32 pk0 = (hh & 0xFFFFu) | (ll << 16);
                const u32 pk1 = (hh >> 16) | (ll & 0xFFFF0000u);
                int mm = i1 - j;
                if (mm >= 0) {
                    if (mm < 512) g_Cp[prow1 + mm] = pk0;
                    else { atomicAdd(&sCs[r1], e0); wbuf[wrow1 + j] = e0; }
                }
                if (mm - 1 >= 0) {
                    if (mm - 1 < 512) g_Cp[prow1 + mm - 1] = pk1;
                    else { atomicAdd(&sCs[r1], e1); wbuf[wrow1 + j + 1] = e1; }
                }
            }
            {
                int p0c = j - i2 + 512;   if (p0c < 0) p0c = 0;
                int p1c = j + 1 - i2 + 512; if (p1c < 0) p1c = 0;
                float l0 = accC[nt][2] + g_P[prow2 + p0c];
                float l1 = accC[nt][3] + g_P[prow2 + p1c];
                if (j     > i2) l0 = -1e30f;
                if (j + 1 > i2) l1 = -1e30f;
                float e0 = __expf(l0), e1 = __expf(l1);
                s2 += e0 + e1;
                u32 hh, ll; split2(e0, e1, hh, ll);
                *(u32*)&Kh[r2*TW + jl] = hh;
                *(u32*)&Kl[r2*TW + jl] = ll;
                const u32 pk0 = (hh & 0xFFFFu) | (ll << 16);
                const u32 pk1 = (hh >> 16) | (ll & 0xFFFF0000u);
                int mm = i2 - j;
                if (mm >= 0) {
                    if (mm < 512) g_Cp[prow2 + mm] = pk0;
                    else { atomicAdd(&sCs[r2], e0); wbuf[wrow2 + j] = e0; }
                }
                if (mm - 1 >= 0) {
                    if (mm - 1 < 512) g_Cp[prow2 + mm - 1] = pk1;
                    else { atomicAdd(&sCs[r2], e1); wbuf[wrow2 + j + 1] = e1; }
                }
            }
        }
        s1 += __shfl_xor_sync(0xffffffffu, s1, 1);
        s1 += __shfl_xor_sync(0xffffffffu, s1, 2);
        s2 += __shfl_xor_sync(0xffffffffu, s2, 1);
        s2 += __shfl_xor_sync(0xffffffffu, s2, 2);
        if ((lane & 3) == 0) { atomicAdd(&sS[r1], s1); atomicAdd(&sS[r2], s2); }

        __syncthreads();   // (4) E tiles ready

        // ---- accO += E @ V via mma (E aliased in Kh/Kl) ----
        #pragma unroll
        for (int ks = 0; ks < 4; ++ks) {
            u32 ah[4], al[4], bh2[2], bl2[2];
            ldmx4(ah, sbase + KH_OFF + (u32)((mrow + lA_r)*TW + ks*16 + lA_c)*2);
            ldmx4(al, sbase + KL_OFF + (u32)((mrow + lA_r)*TW + ks*16 + lA_c)*2);
            #pragma unroll
            for (int nt = 0; nt < 4; ++nt) {
                ldmx2t(bh2, sbase + VH_OFF + (u32)((ks*16 + lBt_r)*TW + n0 + 8*nt)*2);
                ldmx2t(bl2, sbase + VL_OFF + (u32)((ks*16 + lBt_r)*TW + n0 + 8*nt)*2);
                mma16816(accO[nt], ah, bh2);
                mma16816(accO[nt], ah, bl2);
                mma16816(accO[nt], al, bh2);
            }
        }
    }

    __syncthreads();
    if (tid < 64) {
        sInv[tid] = 1.0f / sS[tid];
        sWv0[tid] = Wv[tid];   // Wv_rev[512] = Wv[0][:]
    }

    // ---- D-phase (mma into accO): m in [0, min(512, i0+64)) ----
    const int mEndD = min(512, i0 + 64);
    for (int m0 = 0; m0 < mEndD; m0 += 64) {
        __syncthreads();   // buffers free
        // C chunk: unpack g_Cp -> Kh/Kl, mask m > irow
        #pragma unroll
        for (int l = 0; l < 4; ++l) {
            int e = tid + l * 256;
            int r = e >> 4, m4 = (e & 15) << 2;
            const int irow = i0 + r;
            const int mb = m0 + m4;
            uint4 pp = *(const uint4*)(g_Cp + (size_t)(rowbase + r)*PSTR + mb);
            u32 pa[4] = {pp.x, pp.y, pp.z, pp.w};
            #pragma unroll
            for (int t = 0; t < 4; ++t)
                if (mb + t > irow) pa[t] = 0;
            *(u32*)&Kh[r*TW + m4]     = (pa[0] & 0xFFFFu) | ((pa[1] & 0xFFFFu) << 16);
            *(u32*)&Kh[r*TW + m4 + 2] = (pa[2] & 0xFFFFu) | ((pa[3] & 0xFFFFu) << 16);
            *(u32*)&Kl[r*TW + m4]     = (pa[0] >> 16) | (pa[1] & 0xFFFF0000u);
            *(u32*)&Kl[r*TW + m4 + 2] = (pa[2] >> 16) | (pa[3] & 0xFFFF0000u);
        }
        // Wv_rev chunk: pre-split, pure copy
        #pragma unroll
        for (int l = 0; l < 2; ++l) {
            int e = tid + l * 256;
            int mr = e >> 3, c8 = (e & 7) << 3;
            const size_t ga = (size_t)(m0 + mr)*64 + c8;
            *(uint4*)&Vh[mr*TW + c8] = *(const uint4*)&gWrh[ga];
            *(uint4*)&Vl[mr*TW + c8] = *(const uint4*)&gWrl[ga];
        }
        __syncthreads();
        #pragma unroll
        for (int ks = 0; ks < 4; ++ks) {
            u32 ah[4], al[4], bh2[2], bl2[2];
            ldmx4(ah, sbase + KH_OFF + (u32)((mrow + lA_r)*TW + ks*16 + lA_c)*2);
            ldmx4(al, sbase + KL_OFF + (u32)((mrow + lA_r)*TW + ks*16 + lA_c)*2);
            #pragma unroll
            for (int nt = 0; nt < 4; ++nt) {
                ldmx2t(bh2, sbase + VH_OFF + (u32)((ks*16 + lBt_r)*TW + n0 + 8*nt)*2);
                ldmx2t(bl2, sbase + VL_OFF + (u32)((ks*16 + lBt_r)*TW + n0 + 8*nt)*2);
                mma16816(accO[nt], ah, bh2);
                mma16816(accO[nt], ah, bl2);
                mma16816(accO[nt], al, bh2);
            }
        }
    }
    __syncthreads();   // sInv/sCs/sWv0 stable

    // ---- final output directly from fragments ----
    {
        const float inv1 = sInv[r1], inv2 = sInv[r2];
        const float cs1 = sCs[r1],  cs2 = sCs[r2];
        #pragma unroll
        for (int nt = 0; nt < 4; ++nt) {
            const int c = n0 + 8*nt + 2*(lane & 3);
            const float w00 = (accO[nt][0] + cs1*sWv0[c])   * inv1;
            const float w01 = (accO[nt][1] + cs1*sWv0[c+1]) * inv1;
            const float w10 = (accO[nt][2] + cs2*sWv0[c])   * inv2;
            const float w11 = (accO[nt][3] + cs2*sWv0[c+1]) * inv2;
            *(float2*)(outp + (size_t)(rowbase + r1)*64 + c) = make_float2(w00, w01);
            *(float2*)(outp + (size_t)(rowbase + r2)*64 + c) = make_float2(w10, w11);
        }
    }

    // ---- pass2: weights from g_Cp (unpack hi+lo) ----
    for (int jb = 0; jb < 16; ++jb) {
        const int j0 = jb * 64;
        if (jb > ib) {
            const float4 z = make_float4(0.f, 0.f, 0.f, 0.f);
            for (int e = tid; e < 1024; e += 256) {
                int r = e >> 4, c4 = (e & 15) << 2;
                *(float4*)(wbuf + (size_t)(rowbase + r) * S_LEN + j0 + c4) = z;
            }
            continue;
        }
        for (int e = tid; e < 1024; e += 256) {
            int r = e >> 4, c4 = (e & 15) << 2;
            const int i = i0 + r;
            const size_t row = (size_t)(rowbase + r);
            const size_t addr = row * S_LEN + j0 + c4;
            const size_t prow = row * PSTR;
            const float f = sInv[r];
            float w[4];
            #pragma unroll
            for (int t = 0; t < 4; ++t) {
                const int j = j0 + c4 + t;
                const int mm = i - j;
                float eV = 0.f;
                if (mm >= 0) {
                    if (mm < 512) {
                        const u32 p = g_Cp[prow + mm];
                        eV = __uint_as_float(p << 16) + __uint_as_float(p & 0xFFFF0000u);
                    } else {
                        eV = wbuf[addr + t];   // raw E written in pass1
                    }
                }
                w[t] = eV * f;
            }
            *(float4*)(wbuf + addr) = make_float4(w[0], w[1], w[2], w[3]);
        }
    }
}

// ---------------------------------------------------------------------------
extern "C" void kernel_launch(void* const* d_in, const int* in_sizes, int n_in,
                              void* d_out, int out_size) {
    const float* q  = (const float*)d_in[0];
    const float* k  = (const float*)d_in[1];
    const float* v  = (const float*)d_in[2];
    const float* Wk = (const float*)d_in[3];
    const float* Wv = (const float*)d_in[4];

    float* outp = (float*)d_out;            // (B,H,S,D)
    float* wbuf = outp + OUT_ELEMS;         // (B,H,S,S) weights

    static bool attrs_set = false;
    if (!attrs_set) {
        cudaFuncSetAttribute(kernA,   cudaFuncAttributeMaxDynamicSharedMemorySize, SMEM_A);
        cudaFuncSetAttribute(kernBCD, cudaFuncAttributeMaxDynamicSharedMemorySize, SMEM_BCD);
        attrs_set = true;
    }
    kernSplit<<<4096, 256>>>(k, v);
    kernSplitW<<<32, 256>>>(Wv);
    kernP512<<<256, 256>>>(q, Wk);
    kernA<<<dim3(1024, 4), 256, SMEM_A>>>(q, Wk);
    kernBCD<<<dim3(16, 64), 256, SMEM_BCD>>>(q, Wv, wbuf, outp);
}

// round 17
// speedup vs baseline: 1.0399x; 1.0104x over previous
#include <cuda_runtime.h>
#include <cuda_bf16.h>

#define S_LEN 1024
#define NP 513
#define PSTR 516
#define OUT_ELEMS 4194304
#define NROWS 65536
#define TW 72   // bf16 smem row stride (elements)

typedef unsigned long long ull;
typedef unsigned int u32;

__device__ float g_P[(size_t)NROWS * PSTR];   // P[row,p] = q[row]·Wk[p]
__device__ u32   g_Cp[(size_t)NROWS * PSTR];  // packed bf16 hi/lo of shifted E
__device__ __nv_bfloat16 gKh[OUT_ELEMS], gKl[OUT_ELEMS];
__device__ __nv_bfloat16 gVh[OUT_ELEMS], gVl[OUT_ELEMS];
__device__ __nv_bfloat16 gWrh[512 * 64], gWrl[512 * 64];  // Wv_rev split, [m][d]

// smem byte offsets for kernBCD (E aliases K; C/Wv chunks alias K/V)
#define QH_OFF 0
#define QL_OFF 9216
#define KH_OFF 18432
#define KL_OFF 27648
#define VH_OFF 36864
#define VL_OFF 46080
#define SS_OFF 55296
#define SCS_OFF 55552
#define SINV_OFF 55808
#define SWV0_OFF 56064
#define SMEM_BCD 56320

// smem byte offsets for kernA (tensor)
#define AQH_OFF 0
#define AQL_OFF 9216
#define AWH_OFF 18432
#define AWL_OFF 36864
#define SMEM_A 55296

// ---- tensor helpers ----
__device__ __forceinline__ void ldmx4(u32* r, u32 addr) {
    asm volatile("ldmatrix.sync.aligned.m8n8.x4.shared.b16 {%0,%1,%2,%3}, [%4];"
        : "=r"(r[0]), "=r"(r[1]), "=r"(r[2]), "=r"(r[3]) : "r"(addr));
}
__device__ __forceinline__ void ldmx2(u32* r, u32 addr) {
    asm volatile("ldmatrix.sync.aligned.m8n8.x2.shared.b16 {%0,%1}, [%2];"
        : "=r"(r[0]), "=r"(r[1]) : "r"(addr));
}
__device__ __forceinline__ void ldmx2t(u32* r, u32 addr) {
    asm volatile("ldmatrix.sync.aligned.m8n8.x2.trans.shared.b16 {%0,%1}, [%2];"
        : "=r"(r[0]), "=r"(r[1]) : "r"(addr));
}
__device__ __forceinline__ void mma16816(float* c, const u32* a, const u32* b) {
    asm volatile("mma.sync.aligned.m16n8k16.row.col.f32.bf16.bf16.f32 "
        "{%0,%1,%2,%3}, {%4,%5,%6,%7}, {%8,%9}, {%0,%1,%2,%3};"
        : "+f"(c[0]), "+f"(c[1]), "+f"(c[2]), "+f"(c[3])
        : "r"(a[0]), "r"(a[1]), "r"(a[2]), "r"(a[3]), "r"(b[0]), "r"(b[1]));
}
__device__ __forceinline__ void split2(float x, float y, u32& h, u32& l) {
    __nv_bfloat16 hx = __float2bfloat16(x), hy = __float2bfloat16(y);
    __nv_bfloat162 hh; hh.x = hx; hh.y = hy;
    __nv_bfloat162 ll;
    ll.x = __float2bfloat16(x - __bfloat162float(hx));
    ll.y = __float2bfloat16(y - __bfloat162float(hy));
    h = *(u32*)&hh; l = *(u32*)&ll;
}

// ---------------------------------------------------------------------------
// kernSplit: K,V fp32 -> global bf16 hi/lo (once)
// ---------------------------------------------------------------------------
__global__ void __launch_bounds__(256) kernSplit(const float* __restrict__ k,
                                                 const float* __restrict__ v) {
    const int idx = (blockIdx.x * 256 + threadIdx.x) * 4;
    float4 kv = *(const float4*)(k + idx);
    u32 h0, l0, h1, l1;
    split2(kv.x, kv.y, h0, l0); split2(kv.z, kv.w, h1, l1);
    *(uint2*)&gKh[idx] = make_uint2(h0, h1);
    *(uint2*)&gKl[idx] = make_uint2(l0, l1);
    float4 vv = *(const float4*)(v + idx);
    split2(vv.x, vv.y, h0, l0); split2(vv.z, vv.w, h1, l1);
    *(uint2*)&gVh[idx] = make_uint2(h0, h1);
    *(uint2*)&gVl[idx] = make_uint2(l0, l1);
}

// ---------------------------------------------------------------------------
// kernSplitW: Wv_rev[m][d] = Wv[512-m][d] -> bf16 hi/lo, m in [0,512)
// ---------------------------------------------------------------------------
__global__ void __launch_bounds__(256) kernSplitW(const float* __restrict__ Wv) {
    const int idx = (blockIdx.x * 256 + threadIdx.x) * 4;   // 8192 threads total
    const int m = idx >> 6, d = idx & 63;
    float4 vv = *(const float4*)(Wv + (size_t)(512 - m) * 64 + d);
    u32 h0, l0, h1, l1;
    split2(vv.x, vv.y, h0, l0); split2(vv.z, vv.w, h1, l1);
    *(uint2*)&gWrh[idx] = make_uint2(h0, h1);
    *(uint2*)&gWrl[idx] = make_uint2(l0, l1);
}

// ---------------------------------------------------------------------------
// kernP512: g_P[row, 512] = q[row] · Wk[512]  (fp32 exact; diagonal bias)
// ---------------------------------------------------------------------------
__global__ void __launch_bounds__(256) kernP512(const float* __restrict__ q,
                                                const float* __restrict__ Wk) {
    __shared__ float w512[64];
    const int tid = threadIdx.x;
    if (tid < 64) w512[tid] = Wk[(size_t)512 * 64 + tid];
    __syncthreads();
    const int row = blockIdx.x * 256 + tid;
    const float* qr = q + (size_t)row * 64;
    float s = 0.f;
    #pragma unroll
    for (int c4 = 0; c4 < 64; c4 += 4) {
        float4 vv = *(const float4*)(qr + c4);
        s += vv.x * w512[c4] + vv.y * w512[c4+1] + vv.z * w512[c4+2] + vv.w * w512[c4+3];
    }
    g_P[(size_t)row * PSTR + 512] = s;
}

// ---------------------------------------------------------------------------
// Kernel A (tensor): P = Q @ Wk^T for p in [0,512), 64x128 tiles, bf16 3-split
// ---------------------------------------------------------------------------
__global__ void __launch_bounds__(256) kernA(const float* __restrict__ q,
                                             const float* __restrict__ Wk) {
    const int r0 = blockIdx.x * 64;
    const int p0 = blockIdx.y * 128;
    const int i0 = r0 & (S_LEN - 1);
    if (p0 + 127 < 449 - i0) return;
    extern __shared__ char smemA[];
    __nv_bfloat16* Qh = (__nv_bfloat16*)(smemA + AQH_OFF);
    __nv_bfloat16* Ql = (__nv_bfloat16*)(smemA + AQL_OFF);
    __nv_bfloat16* Wh = (__nv_bfloat16*)(smemA + AWH_OFF);
    __nv_bfloat16* Wl = (__nv_bfloat16*)(smemA + AWL_OFF);
    const u32 sbase = (u32)__cvta_generic_to_shared(smemA);
    const int tid = threadIdx.x;
    const int wid = tid >> 5, lane = tid & 31;

    #pragma unroll
    for (int l = 0; l < 4; ++l) {
        int e = tid + l * 256;
        int r = e >> 4, c4 = (e & 15) << 2;
        float4 vv = *(const float4*)(q + (size_t)(r0 + r) * 64 + c4);
        u32 h0, l0, h1, l1;
        split2(vv.x, vv.y, h0, l0); split2(vv.z, vv.w, h1, l1);
        *(u32*)&Qh[r*TW + c4] = h0; *(u32*)&Qh[r*TW + c4 + 2] = h1;
        *(u32*)&Ql[r*TW + c4] = l0; *(u32*)&Ql[r*TW + c4 + 2] = l1;
    }
    #pragma unroll
    for (int l = 0; l < 8; ++l) {
        int e = tid + l * 256;
        int r = e >> 4, c4 = (e & 15) << 2;
        float4 vv = *(const float4*)(Wk + (size_t)(p0 + r) * 64 + c4);
        u32 h0, l0, h1, l1;
        split2(vv.x, vv.y, h0, l0); split2(vv.z, vv.w, h1, l1);
        *(u32*)&Wh[r*TW + c4] = h0; *(u32*)&Wh[r*TW + c4 + 2] = h1;
        *(u32*)&Wl[r*TW + c4] = l0; *(u32*)&Wl[r*TW + c4 + 2] = l1;
    }
    __syncthreads();

    const int mrow = 16 * (wid & 3);
    const int n0   = 64 * (wid >> 2);
    const int lA_r = (lane & 7) + ((lane >> 3) & 1) * 8;
    const int lA_c = ((lane >> 4) & 1) * 8;
    const int lB_r = (lane & 7);
    const int lB_c = ((lane >> 3) & 1) * 8;

    float accP[8][4] = {};
    #pragma unroll
    for (int ks = 0; ks < 4; ++ks) {
        u32 ah[4], al[4], bh2[2], bl2[2];
        ldmx4(ah, sbase + AQH_OFF + (u32)((mrow + lA_r)*TW + ks*16 + lA_c)*2);
        ldmx4(al, sbase + AQL_OFF + (u32)((mrow + lA_r)*TW + ks*16 + lA_c)*2);
        #pragma unroll
        for (int nt = 0; nt < 8; ++nt) {
            ldmx2(bh2, sbase + AWH_OFF + (u32)((n0 + 8*nt + lB_r)*TW + ks*16 + lB_c)*2);
            ldmx2(bl2, sbase + AWL_OFF + (u32)((n0 + 8*nt + lB_r)*TW + ks*16 + lB_c)*2);
            mma16816(accP[nt], ah, bh2);
            mma16816(accP[nt], ah, bl2);
            mma16816(accP[nt], al, bh2);
        }
    }

    const int r1 = mrow + (lane >> 2), r2 = r1 + 8;
    const size_t row1 = (size_t)(r0 + r1) * PSTR;
    const size_t row2 = (size_t)(r0 + r2) * PSTR;
    #pragma unroll
    for (int nt = 0; nt < 8; ++nt) {
        const int p = p0 + n0 + 8*nt + 2*(lane & 3);
        *(float2*)(g_P + row1 + p) = make_float2(accP[nt][0], accP[nt][1]);
        *(float2*)(g_P + row2 + p) = make_float2(accP[nt][2], accP[nt][3]);
    }
}

// ---------------------------------------------------------------------------
// Fused B+C+D: all three GEMMs on tensor cores; separate accD (round-14 best).
// ---------------------------------------------------------------------------
__global__ void __launch_bounds__(256) kernBCD(const float* __restrict__ q,
                                               const float* __restrict__ Wv,
                                               float* __restrict__ wbuf,
                                               float* __restrict__ outp) {
    extern __shared__ char smem[];
    __nv_bfloat16* Qh = (__nv_bfloat16*)(smem + QH_OFF);
    __nv_bfloat16* Ql = (__nv_bfloat16*)(smem + QL_OFF);
    __nv_bfloat16* Kh = (__nv_bfloat16*)(smem + KH_OFF);   // K^T; E; C-chunk
    __nv_bfloat16* Kl = (__nv_bfloat16*)(smem + KL_OFF);
    __nv_bfloat16* Vh = (__nv_bfloat16*)(smem + VH_OFF);   // V; Wv-chunk
    __nv_bfloat16* Vl = (__nv_bfloat16*)(smem + VL_OFF);
    float* sS   = (float*)(smem + SS_OFF);
    float* sCs  = (float*)(smem + SCS_OFF);
    float* sInv = (float*)(smem + SINV_OFF);
    float* sWv0 = (float*)(smem + SWV0_OFF);
    const u32 sbase = (u32)__cvta_generic_to_shared(smem);

    const int bh = blockIdx.y;
    const int ib = 15 - (int)blockIdx.x;
    const int i0 = ib * 64;
    const int rowbase = bh * S_LEN + i0;
    const int tid = threadIdx.x;
    const int wid = tid >> 5, lane = tid & 31;
    const int mrow = 16 * (wid & 3);
    const int n0   = 32 * (wid >> 2);

    // ---- Q prep: split into Qh/Ql ----
    #pragma unroll
    for (int l = 0; l < 4; ++l) {
        int e = tid + l * 256;
        int r = e >> 4, c4 = (e & 15) << 2;
        float4 vv = *(const float4*)(q + (size_t)(rowbase + r) * 64 + c4);
        u32 h0, l0, h1, l1;
        split2(vv.x, vv.y, h0, l0); split2(vv.z, vv.w, h1, l1);
        *(u32*)&Qh[r*TW + c4] = h0; *(u32*)&Qh[r*TW + c4 + 2] = h1;
        *(u32*)&Ql[r*TW + c4] = l0; *(u32*)&Ql[r*TW + c4 + 2] = l1;
    }
    if (tid < 64) { sS[tid] = 0.f; sCs[tid] = 0.f; }

    const int r1 = mrow + (lane >> 2), r2 = r1 + 8;
    const int i1 = i0 + r1, i2 = i0 + r2;
    const size_t prow1 = (size_t)(rowbase + r1) * PSTR;
    const size_t prow2 = (size_t)(rowbase + r2) * PSTR;
    const size_t wrow1 = (size_t)(rowbase + r1) * S_LEN;
    const size_t wrow2 = (size_t)(rowbase + r2) * S_LEN;

    const int lA_r = (lane & 7) + ((lane >> 3) & 1) * 8;
    const int lA_c = ((lane >> 4) & 1) * 8;
    const int lB_r = (lane & 7);
    const int lB_c = ((lane >> 3) & 1) * 8;
    const int lBt_r = (lane & 7) + ((lane >> 3) & 1) * 8;

    float accO[4][4] = {};

    // ================= pass1 =================
    for (int jb = 0; jb <= ib; ++jb) {
        const int j0 = jb * 64;
        __syncthreads();   // (1) prev E@V mma done

        #pragma unroll
        for (int l = 0; l < 2; ++l) {
            int e = tid + l * 256;
            int r = e >> 3, c8 = (e & 7) << 3;
            const size_t ga = (size_t)(bh*S_LEN + j0 + r)*64 + c8;
            *(uint4*)&Kh[r*TW + c8] = *(const uint4*)&gKh[ga];
            *(uint4*)&Kl[r*TW + c8] = *(const uint4*)&gKl[ga];
            *(uint4*)&Vh[r*TW + c8] = *(const uint4*)&gVh[ga];
            *(uint4*)&Vl[r*TW + c8] = *(const uint4*)&gVl[ga];
        }
        __syncthreads();   // (2) tiles ready

        // ---- QK^T via mma ----
        float accC[4][4] = {};
        #pragma unroll
        for (int ks = 0; ks < 4; ++ks) {
            u32 ah[4], al[4], bh2[2], bl2[2];
            ldmx4(ah, sbase + QH_OFF + (u32)((mrow + lA_r)*TW + ks*16 + lA_c)*2);
            ldmx4(al, sbase + QL_OFF + (u32)((mrow + lA_r)*TW + ks*16 + lA_c)*2);
            #pragma unroll
            for (int nt = 0; nt < 4; ++nt) {
                ldmx2(bh2, sbase + KH_OFF + (u32)((n0 + 8*nt + lB_r)*TW + ks*16 + lB_c)*2);
                ldmx2(bl2, sbase + KL_OFF + (u32)((n0 + 8*nt + lB_r)*TW + ks*16 + lB_c)*2);
                mma16816(accC[nt], ah, bh2);
                mma16816(accC[nt], ah, bl2);
                mma16816(accC[nt], al, bh2);
            }
        }
        __syncthreads();   // (3) K reads done -> E may overwrite Kh/Kl

        // ---- bias + mask + exp + rowsum + packed scatter + E->smem ----
        float s1 = 0.f, s2 = 0.f;
        #pragma unroll
        for (int nt = 0; nt < 4; ++nt) {
            const int jl = n0 + 8*nt + 2*(lane & 3);
            const int j  = j0 + jl;
            {
                int p0c = j - i1 + 512;   if (p0c < 0) p0c = 0;
                int p1c = j + 1 - i1 + 512; if (p1c < 0) p1c = 0;
                float l0 = accC[nt][0] + g_P[prow1 + p0c];
                float l1 = accC[nt][1] + g_P[prow1 + p1c];
                if (j     > i1) l0 = -1e30f;
                if (j + 1 > i1) l1 = -1e30f;
                float e0 = __expf(l0), e1 = __expf(l1);
                s1 += e0 + e1;
                u32 hh, ll; split2(e0, e1, hh, ll);
                *(u32*)&Kh[r1*TW + jl] = hh;
                *(u32*)&Kl[r1*TW + jl] = ll;
                const u32 pk0 = (hh & 0xFFFFu) | (ll << 16);
                const u32 pk1 = (hh >> 16) | (ll & 0xFFFF0000u);
                int mm = i1 - j;
                if (mm >= 0) {
                    if (mm < 512) g_Cp[prow1 + mm] = pk0;
                    else { atomicAdd(&sCs[r1], e0); wbuf[wrow1 + j] = e0; }
                }
                if (mm - 1 >= 0) {
                    if (mm - 1 < 512) g_Cp[prow1 + mm - 1] = pk1;
                    else { atomicAdd(&sCs[r1], e1); wbuf[wrow1 + j + 1] = e1; }
                }
            }
            {
                int p0c = j - i2 + 512;   if (p0c < 0) p0c = 0;
                int p1c = j + 1 - i2 + 512; if (p1c < 0) p1c = 0;
                float l0 = accC[nt][2] + g_P[prow2 + p0c];
                float l1 = accC[nt][3] + g_P[prow2 + p1c];
                if (j     > i2) l0 = -1e30f;
                if (j + 1 > i2) l1 = -1e30f;
                float e0 = __expf(l0), e1 = __expf(l1);
                s2 += e0 + e1;
                u32 hh, ll; split2(e0, e1, hh, ll);
                *(u32*)&Kh[r2*TW + jl] = hh;
                *(u32*)&Kl[r2*TW + jl] = ll;
                const u32 pk0 = (hh & 0xFFFFu) | (ll << 16);
                const u32 pk1 = (hh >> 16) | (ll & 0xFFFF0000u);
                int mm = i2 - j;
                if (mm >= 0) {
                    if (mm < 512) g_Cp[prow2 + mm] = pk0;
                    else { atomicAdd(&sCs[r2], e0); wbuf[wrow2 + j] = e0; }
                }
                if (mm - 1 >= 0) {
                    if (mm - 1 < 512) g_Cp[prow2 + mm - 1] = pk1;
                    else { atomicAdd(&sCs[r2], e1); wbuf[wrow2 + j + 1] = e1; }
                }
            }
        }
        s1 += __shfl_xor_sync(0xffffffffu, s1, 1);
        s1 += __shfl_xor_sync(0xffffffffu, s1, 2);
        s2 += __shfl_xor_sync(0xffffffffu, s2, 1);
        s2 += __shfl_xor_sync(0xffffffffu, s2, 2);
        if ((lane & 3) == 0) { atomicAdd(&sS[r1], s1); atomicAdd(&sS[r2], s2); }

        __syncthreads();   // (4) E tiles ready

        // ---- accO += E @ V via mma (E aliased in Kh/Kl) ----
        #pragma unroll
        for (int ks = 0; ks < 4; ++ks) {
            u32 ah[4], al[4], bh2[2], bl2[2];
            ldmx4(ah, sbase + KH_OFF + (u32)((mrow + lA_r)*TW + ks*16 + lA_c)*2);
            ldmx4(al, sbase + KL_OFF + (u32)((mrow + lA_r)*TW + ks*16 + lA_c)*2);
            #pragma unroll
            for (int nt = 0; nt < 4; ++nt) {
                ldmx2t(bh2, sbase + VH_OFF + (u32)((ks*16 + lBt_r)*TW + n0 + 8*nt)*2);
                ldmx2t(bl2, sbase + VL_OFF + (u32)((ks*16 + lBt_r)*TW + n0 + 8*nt)*2);
                mma16816(accO[nt], ah, bh2);
                mma16816(accO[nt], ah, bl2);
                mma16816(accO[nt], al, bh2);
            }
        }
    }

    __syncthreads();
    if (tid < 64) {
        sInv[tid] = 1.0f / sS[tid];
        sWv0[tid] = Wv[tid];   // Wv_rev[512] = Wv[0][:]
    }

    // ---- D-phase (mma, separate accD): m in [0, min(512, i0+64)) ----
    float accD[4][4] = {};
    const int mEndD = min(512, i0 + 64);
    for (int m0 = 0; m0 < mEndD; m0 += 64) {
        __syncthreads();   // buffers free
        // C chunk: unpack g_Cp -> Kh/Kl, mask m > irow
        #pragma unroll
        for (int l = 0; l < 4; ++l) {
            int e = tid + l * 256;
            int r = e >> 4, m4 = (e & 15) << 2;
            const int irow = i0 + r;
            const int mb = m0 + m4;
            uint4 pp = *(const uint4*)(g_Cp + (size_t)(rowbase + r)*PSTR + mb);
            u32 pa[4] = {pp.x, pp.y, pp.z, pp.w};
            #pragma unroll
            for (int t = 0; t < 4; ++t)
                if (mb + t > irow) pa[t] = 0;
            *(u32*)&Kh[r*TW + m4]     = (pa[0] & 0xFFFFu) | ((pa[1] & 0xFFFFu) << 16);
            *(u32*)&Kh[r*TW + m4 + 2] = (pa[2] & 0xFFFFu) | ((pa[3] & 0xFFFFu) << 16);
            *(u32*)&Kl[r*TW + m4]     = (pa[0] >> 16) | (pa[1] & 0xFFFF0000u);
            *(u32*)&Kl[r*TW + m4 + 2] = (pa[2] >> 16) | (pa[3] & 0xFFFF0000u);
        }
        // Wv_rev chunk: pre-split, pure copy
        #pragma unroll
        for (int l = 0; l < 2; ++l) {
            int e = tid + l * 256;
            int mr = e >> 3, c8 = (e & 7) << 3;
            const size_t ga = (size_t)(m0 + mr)*64 + c8;
            *(uint4*)&Vh[mr*TW + c8] = *(const uint4*)&gWrh[ga];
            *(uint4*)&Vl[mr*TW + c8] = *(const uint4*)&gWrl[ga];
        }
        __syncthreads();
        #pragma unroll
        for (int ks = 0; ks < 4; ++ks) {
            u32 ah[4], al[4], bh2[2], bl2[2];
            ldmx4(ah, sbase + KH_OFF + (u32)((mrow + lA_r)*TW + ks*16 + lA_c)*2);
            ldmx4(al, sbase + KL_OFF + (u32)((mrow + lA_r)*TW + ks*16 + lA_c)*2);
            #pragma unroll
            for (int nt = 0; nt < 4; ++nt) {
                ldmx2t(bh2, sbase + VH_OFF + (u32)((ks*16 + lBt_r)*TW + n0 + 8*nt)*2);
                ldmx2t(bl2, sbase + VL_OFF + (u32)((ks*16 + lBt_r)*TW + n0 + 8*nt)*2);
                mma16816(accD[nt], ah, bh2);
                mma16816(accD[nt], ah, bl2);
                mma16816(accD[nt], al, bh2);
            }
        }
    }
    __syncthreads();   // sInv/sCs/sWv0 stable

    // ---- final output directly from fragments ----
    {
        const float inv1 = sInv[r1], inv2 = sInv[r2];
        const float cs1 = sCs[r1],  cs2 = sCs[r2];
        #pragma unroll
        for (int nt = 0; nt < 4; ++nt) {
            const int c = n0 + 8*nt + 2*(lane & 3);
            const float w00 = (accO[nt][0] + accD[nt][0] + cs1*sWv0[c])   * inv1;
            const float w01 = (accO[nt][1] + accD[nt][1] + cs1*sWv0[c+1]) * inv1;
            const float w10 = (accO[nt][2] + accD[nt][2] + cs2*sWv0[c])   * inv2;
            const float w11 = (accO[nt][3] + accD[nt][3] + cs2*sWv0[c+1]) * inv2;
            *(float2*)(outp + (size_t)(rowbase + r1)*64 + c) = make_float2(w00, w01);
            *(float2*)(outp + (size_t)(rowbase + r2)*64 + c) = make_float2(w10, w11);
        }
    }

    // ---- pass2: weights from g_Cp (unpack hi+lo) ----
    for (int jb = 0; jb < 16; ++jb) {
        const int j0 = jb * 64;
        if (jb > ib) {
            const float4 z = make_float4(0.f, 0.f, 0.f, 0.f);
            for (int e = tid; e < 1024; e += 256) {
                int r = e >> 4, c4 = (e & 15) << 2;
                *(float4*)(wbuf + (size_t)(rowbase + r) * S_LEN + j0 + c4) = z;
            }
            continue;
        }
        for (int e = tid; e < 1024; e += 256) {
            int r = e >> 4, c4 = (e & 15) << 2;
            const int i = i0 + r;
            const size_t row = (size_t)(rowbase + r);
            const size_t addr = row * S_LEN + j0 + c4;
            const size_t prow = row * PSTR;
            const float f = sInv[r];
            float w[4];
            #pragma unroll
            for (int t = 0; t < 4; ++t) {
                const int j = j0 + c4 + t;
                const int mm = i - j;
                float eV = 0.f;
                if (mm >= 0) {
                    if (mm < 512) {
                        const u32 p = g_Cp[prow + mm];
                        eV = __uint_as_float(p << 16) + __uint_as_float(p & 0xFFFF0000u);
                    } else {
                        eV = wbuf[addr + t];   // raw E written in pass1
                    }
                }
                w[t] = eV * f;
            }
            *(float4*)(wbuf + addr) = make_float4(w[0], w[1], w[2], w[3]);
        }
    }
}

// ---------------------------------------------------------------------------
extern "C" void kernel_launch(void* const* d_in, const int* in_sizes, int n_in,
                              void* d_out, int out_size) {
    const float* q  = (const float*)d_in[0];
    const float* k  = (const float*)d_in[1];
    const float* v  = (const float*)d_in[2];
    const float* Wk = (const float*)d_in[3];
    const float* Wv = (const float*)d_in[4];

    float* outp = (float*)d_out;            // (B,H,S,D)
    float* wbuf = outp + OUT_ELEMS;         // (B,H,S,S) weights

    static bool attrs_set = false;
    if (!attrs_set) {
        cudaFuncSetAttribute(kernA,   cudaFuncAttributeMaxDynamicSharedMemorySize, SMEM_A);
        cudaFuncSetAttribute(kernBCD, cudaFuncAttributeMaxDynamicSharedMemorySize, SMEM_BCD);
        attrs_set = true;
    }
    kernSplit<<<4096, 256>>>(k, v);
    kernSplitW<<<32, 256>>>(Wv);
    kernP512<<<256, 256>>>(q, Wk);
    kernA<<<dim3(1024, 4), 256, SMEM_A>>>(q, Wk);
    kernBCD<<<dim3(16, 64), 256, SMEM_BCD>>>(q, Wv, wbuf, outp);
}